// round 4
// baseline (speedup 1.0000x reference)
#include <cuda_runtime.h>
#include <math.h>
#include <stdint.h>

#define FULLMASK 0xffffffffu
#define NCTA 256

// ---------------- persistent device scratch ----------------
__device__ float g_W0T[1536 * 2048];      // layer0 weights [k][j*4+gate]
__device__ float g_W1T[1024 * 2048];      // layer1 weights [k][j*4+gate]
__device__ float g_b0[2048];
__device__ float g_b1[2048];
__device__ float g_embT[64 * 512 * 32];   // embeddings [t][k][b]
__device__ float g_f1[32 * 512];
__device__ float g_h0T[512 * 32];         // states [j][b]
__device__ float g_h1T[512 * 32];
__device__ float g_c0T[512 * 32];
__device__ float g_c1T[512 * 32];
__device__ float g_ctxT[512 * 32];
__device__ float g_part0[2048 * 32 * 32]; // [jj][ks][b]
__device__ float g_part1[2048 * 32 * 32];
__device__ float g_hs[2048 * 512];        // FC input, row m = t*32+b

// barrier state
__device__ unsigned g_cnt = 0;
__device__ volatile unsigned g_gen = 0;

// ---------------- helpers ----------------
static __device__ __forceinline__ float sigmoidf_(float x) { return 1.f / (1.f + expf(-x)); }

static __device__ __forceinline__ float warp_sum(float v) {
#pragma unroll
    for (int o = 16; o; o >>= 1) v += __shfl_xor_sync(FULLMASK, v, o);
    return v;
}

static __device__ __forceinline__ unsigned long long pack2(float lo, float hi) {
    unsigned long long r;
    asm("mov.b64 %0, {%1, %2};" : "=l"(r) : "f"(lo), "f"(hi));
    return r;
}
static __device__ __forceinline__ void unpack2(unsigned long long v, float& lo, float& hi) {
    asm("mov.b64 {%0, %1}, %2;" : "=f"(lo), "=f"(hi) : "l"(v));
}
#define FMA2(acc, a, b) asm("fma.rn.f32x2 %0, %1, %2, %0;" : "+l"(acc) : "l"(a), "l"(b))

// software grid barrier (all NCTA CTAs co-resident)
static __device__ __forceinline__ void gsync() {
    __syncthreads();
    if (threadIdx.x == 0) {
        __threadfence();                       // release my writes to L2
        unsigned old = g_gen;
        if (atomicAdd(&g_cnt, 1u) == NCTA - 1u) {
            g_cnt = 0;
            __threadfence();
            g_gen = old + 1u;
        } else {
            while (g_gen == old) {}
        }
        __threadfence();                       // acquire: invalidate L1 (CCTL.IVALL)
    }
    __syncthreads();
}

// ---------------- weight preprocessing (tiled transpose) ----------------
__global__ __launch_bounds__(256) void prepW0_kernel(const float* __restrict__ wih0,
                                                     const float* __restrict__ whh0) {
    __shared__ float tile[32][33];
    int jj0 = blockIdx.x * 32;     // 64 tiles
    int k0 = blockIdx.y * 32;      // 48 tiles
    int tx = threadIdx.x & 31, ty = threadIdx.x >> 5;
    for (int jjl = ty; jjl < 32; jjl += 8) {
        int jj = jj0 + jjl;
        int j = jj >> 2, g = jj & 3;
        int row = g * 512 + j;
        int k = k0 + tx;
        float v = (k < 1024) ? wih0[row * 1024 + k] : whh0[row * 512 + (k - 1024)];
        tile[jjl][tx] = v;
    }
    __syncthreads();
    for (int kl = ty; kl < 32; kl += 8) {
        g_W0T[(size_t)(k0 + kl) * 2048 + jj0 + tx] = tile[tx][kl];
    }
}

__global__ __launch_bounds__(256) void prepW1_kernel(const float* __restrict__ wih1,
                                                     const float* __restrict__ whh1) {
    __shared__ float tile[32][33];
    int jj0 = blockIdx.x * 32;     // 64 tiles
    int k0 = blockIdx.y * 32;      // 32 tiles
    int tx = threadIdx.x & 31, ty = threadIdx.x >> 5;
    for (int jjl = ty; jjl < 32; jjl += 8) {
        int jj = jj0 + jjl;
        int j = jj >> 2, g = jj & 3;
        int row = g * 512 + j;
        int k = k0 + tx;
        float v = (k < 512) ? wih1[row * 512 + k] : whh1[row * 512 + (k - 512)];
        tile[jjl][tx] = v;
    }
    __syncthreads();
    for (int kl = ty; kl < 32; kl += 8) {
        g_W1T[(size_t)(k0 + kl) * 2048 + jj0 + tx] = tile[tx][kl];
    }
}

__global__ __launch_bounds__(256) void prepB_kernel(const float* __restrict__ bih0,
                                                    const float* __restrict__ bhh0,
                                                    const float* __restrict__ bih1,
                                                    const float* __restrict__ bhh1) {
    int jj = blockIdx.x * 256 + threadIdx.x;
    int j = jj >> 2, g = jj & 3;
    int row = g * 512 + j;
    g_b0[jj] = bih0[row] + bhh0[row];
    g_b1[jj] = bih1[row] + bhh1[row];
}

// ---------------- embedding gather: embT[t][k][b] ----------------
__global__ __launch_bounds__(256) void embed_kernel(const int* __restrict__ cap,
                                                    const float* __restrict__ table) {
    int idx = blockIdx.x * 256 + threadIdx.x;
    int b = idx >> 15;
    int t = (idx >> 9) & 63;
    int k = idx & 511;
    int tok = cap[b * 64 + t];
    g_embT[(t * 512 + k) * 32 + b] = table[(size_t)tok * 512 + k];
}

// ---------------- feature MLP ----------------
__global__ __launch_bounds__(256) void feat1_kernel(const float* __restrict__ features,
                                                    const float* __restrict__ w,
                                                    const float* __restrict__ bias) {
    int gid = blockIdx.x * 8 + (threadIdx.x >> 5);
    int lane = threadIdx.x & 31;
    int b = gid >> 9, j = gid & 511;
    const float* fr = features + b * 2048;
    const float* wr = w + j * 2048;
    float a = 0.f;
    for (int k = lane; k < 2048; k += 32) a = fmaf(fr[k], wr[k], a);
    a = warp_sum(a);
    if (!lane) g_f1[gid] = fmaxf(a + bias[j], 0.f);
}

__global__ __launch_bounds__(256) void feat2_kernel(const float* __restrict__ w,
                                                    const float* __restrict__ bias) {
    int gid = blockIdx.x * 8 + (threadIdx.x >> 5);
    int lane = threadIdx.x & 31;
    int b = gid >> 9, j = gid & 511;
    const float* fr = g_f1 + b * 512;
    const float* wr = w + j * 512;
    float a = 0.f;
    for (int k = lane; k < 512; k += 32) a = fmaf(fr[k], wr[k], a);
    a = warp_sum(a);
    if (!lane) {
        float v = a + bias[j];
        int jb = j * 32 + b;
        g_h0T[jb] = v;
        g_h1T[jb] = v;
        g_c0T[jb] = v;
        g_c1T[jb] = v;
    }
}

// ---------------- persistent recurrence phases ----------------
static __device__ void attn_phase(float* sbuf, const float* __restrict__ enc, int b, int tid) {
    float* q = sbuf;            // 512
    float* sc = sbuf + 512;     // 196
    float* redv = sbuf + 720;   // 16
    int lane = tid & 31, wid = tid >> 5;

    for (int i = tid; i < 512; i += 256) q[i] = g_h1T[i * 32 + b];
    __syncthreads();

    for (int s = wid; s < 196; s += 8) {
        const float* e = enc + ((size_t)b * 196 + s) * 512;
        float a = 0.f;
        for (int k = lane; k < 512; k += 32) a = fmaf(q[k], e[k], a);
        a = warp_sum(a);
        if (!lane) sc[s] = a * 0.04419417382415922f;
    }
    __syncthreads();

    float v = (tid < 196) ? sc[tid] : -1e30f;
    float m = v;
#pragma unroll
    for (int o = 16; o; o >>= 1) m = fmaxf(m, __shfl_xor_sync(FULLMASK, m, o));
    if (!lane) redv[wid] = m;
    __syncthreads();
    m = redv[0];
#pragma unroll
    for (int i = 1; i < 8; i++) m = fmaxf(m, redv[i]);
    float ev = (tid < 196) ? expf(v - m) : 0.f;
    float s = warp_sum(ev);
    if (!lane) redv[8 + wid] = s;
    __syncthreads();
    s = 0.f;
#pragma unroll
    for (int i = 0; i < 8; i++) s += redv[8 + i];
    if (tid < 196) sc[tid] = ev / s;
    __syncthreads();

    for (int j = tid; j < 512; j += 256) {
        const float* e = enc + (size_t)b * 196 * 512 + j;
        float a = 0.f;
#pragma unroll 4
        for (int ss = 0; ss < 196; ss++) a = fmaf(sc[ss], e[(size_t)ss * 512], a);
        g_ctxT[j * 32 + b] = a;
    }
}

// mm0: jx = cta&7, ks = cta>>3 (32 chunks of 48)
static __device__ void mm0_phase(float* xs, int t, int cta, int tid) {
    int jx = cta & 7, ks = cta >> 3;
    int j = tid & 63, bg = tid >> 6;

    const float* embt = g_embT + t * (512 * 32);
    for (int i = tid; i < 48 * 32; i += 256) {
        int kl = i >> 5, b = i & 31;
        int kk = ks * 48 + kl;
        float v;
        if (kk < 512)        v = embt[kk * 32 + b];
        else if (kk < 1024)  v = g_ctxT[(kk - 512) * 32 + b];
        else                 v = g_h0T[(kk - 1024) * 32 + b];
        xs[i] = v;
    }
    __syncthreads();

    int jjbase = (jx * 64 + j) * 4;
    const float4* W = (const float4*)(g_W0T + (size_t)(ks * 48) * 2048 + jjbase);

    unsigned long long acc[4][4];
#pragma unroll
    for (int g = 0; g < 4; g++)
#pragma unroll
        for (int p = 0; p < 4; p++) acc[g][p] = 0ull;

    const float* xr = xs + bg * 8;
#pragma unroll 4
    for (int k = 0; k < 48; k++) {
        float4 w = W[(size_t)k * 512];
        unsigned long long wx = pack2(w.x, w.x);
        unsigned long long wy = pack2(w.y, w.y);
        unsigned long long wz = pack2(w.z, w.z);
        unsigned long long ww = pack2(w.w, w.w);
        const unsigned long long* xp = (const unsigned long long*)(xr + k * 32);
#pragma unroll
        for (int p = 0; p < 4; p++) {
            unsigned long long xv = xp[p];
            FMA2(acc[0][p], wx, xv);
            FMA2(acc[1][p], wy, xv);
            FMA2(acc[2][p], wz, xv);
            FMA2(acc[3][p], ww, xv);
        }
    }

#pragma unroll
    for (int g = 0; g < 4; g++) {
        float* dst = g_part0 + ((size_t)(jjbase + g) * 32 + ks) * 32 + bg * 8;
#pragma unroll
        for (int p = 0; p < 4; p++) {
            float lo, hi;
            unpack2(acc[g][p], lo, hi);
            *(float2*)(dst + 2 * p) = make_float2(lo, hi);
        }
    }
}

// mm1: jx = cta&7, ks = cta>>3 (32 chunks of 32)
static __device__ void mm1_phase(float* xs, int cta, int tid) {
    int jx = cta & 7, ks = cta >> 3;
    int j = tid & 63, bg = tid >> 6;

    for (int i = tid; i < 32 * 32; i += 256) {
        int kl = i >> 5, b = i & 31;
        int kk = ks * 32 + kl;
        float v = (kk < 512) ? g_h0T[kk * 32 + b] : g_h1T[(kk - 512) * 32 + b];
        xs[i] = v;
    }
    __syncthreads();

    int jjbase = (jx * 64 + j) * 4;
    const float4* W = (const float4*)(g_W1T + (size_t)(ks * 32) * 2048 + jjbase);

    unsigned long long acc[4][4];
#pragma unroll
    for (int g = 0; g < 4; g++)
#pragma unroll
        for (int p = 0; p < 4; p++) acc[g][p] = 0ull;

    const float* xr = xs + bg * 8;
#pragma unroll 4
    for (int k = 0; k < 32; k++) {
        float4 w = W[(size_t)k * 512];
        unsigned long long wx = pack2(w.x, w.x);
        unsigned long long wy = pack2(w.y, w.y);
        unsigned long long wz = pack2(w.z, w.z);
        unsigned long long ww = pack2(w.w, w.w);
        const unsigned long long* xp = (const unsigned long long*)(xr + k * 32);
#pragma unroll
        for (int p = 0; p < 4; p++) {
            unsigned long long xv = xp[p];
            FMA2(acc[0][p], wx, xv);
            FMA2(acc[1][p], wy, xv);
            FMA2(acc[2][p], wz, xv);
            FMA2(acc[3][p], ww, xv);
        }
    }

#pragma unroll
    for (int g = 0; g < 4; g++) {
        float* dst = g_part1 + ((size_t)(jjbase + g) * 32 + ks) * 32 + bg * 8;
#pragma unroll
        for (int p = 0; p < 4; p++) {
            float lo, hi;
            unpack2(acc[g][p], lo, hi);
            *(float2*)(dst + 2 * p) = make_float2(lo, hi);
        }
    }
}

static __device__ void red0_phase(int cta, int tid) {
    int idx = cta * 256 + tid;     // < 16384
    int j = idx >> 5, b = idx & 31;
    float4 bs = ((const float4*)g_b0)[j];
    float s0 = bs.x, s1 = bs.y, s2 = bs.z, s3 = bs.w;
    const float* p = g_part0 + (size_t)(j * 4) * 1024 + b;
#pragma unroll 8
    for (int ks = 0; ks < 32; ks++) {
        s0 += p[ks * 32];
        s1 += p[1024 + ks * 32];
        s2 += p[2048 + ks * 32];
        s3 += p[3072 + ks * 32];
    }
    float gi = sigmoidf_(s0);
    float gf = sigmoidf_(s1);
    float gg = tanhf(s2);
    float go = sigmoidf_(s3);
    int jb = j * 32 + b;
    float c2 = gf * g_c0T[jb] + gi * gg;
    g_c0T[jb] = c2;
    g_h0T[jb] = go * tanhf(c2);
}

static __device__ void red1_phase(int t, int cta, int tid) {
    int idx = cta * 256 + tid;     // < 16384
    int j = idx >> 5, b = idx & 31;
    float4 bs = ((const float4*)g_b1)[j];
    float s0 = bs.x, s1 = bs.y, s2 = bs.z, s3 = bs.w;
    const float* p = g_part1 + (size_t)(j * 4) * 1024 + b;
#pragma unroll 8
    for (int ks = 0; ks < 32; ks++) {
        s0 += p[ks * 32];
        s1 += p[1024 + ks * 32];
        s2 += p[2048 + ks * 32];
        s3 += p[3072 + ks * 32];
    }
    float gi = sigmoidf_(s0);
    float gf = sigmoidf_(s1);
    float gg = tanhf(s2);
    float go = sigmoidf_(s3);
    int jb = j * 32 + b;
    float c2 = gf * g_c1T[jb] + gi * gg;
    g_c1T[jb] = c2;
    float h = go * tanhf(c2);
    g_h1T[jb] = h;
    g_hs[((size_t)t * 32 + b) * 512 + j] = h;
}

__global__ __launch_bounds__(256, 2) void rnn_kernel(const float* __restrict__ enc) {
    __shared__ float sbuf[1536];
    int cta = blockIdx.x, tid = threadIdx.x;

    for (int t = 0; t < 64; t++) {
        if (cta < 32) attn_phase(sbuf, enc, cta, tid);
        gsync();
        mm0_phase(sbuf, t, cta, tid);
        gsync();
        if (cta < 64) red0_phase(cta, tid);
        gsync();
        mm1_phase(sbuf, cta, tid);
        gsync();
        if (cta < 64) red1_phase(t, cta, tid);
        gsync();
    }
}

// ---------------- final FC: [2048,512] x [512,32000] + bias ----------------
__global__ __launch_bounds__(256) void fc_kernel(const float* __restrict__ fcw,
                                                 const float* __restrict__ fcb,
                                                 float* __restrict__ out) {
    __shared__ float As[16][132];
    __shared__ float Bs[16][132];
    int tid = threadIdx.x;
    int mb = blockIdx.y * 128, nb = blockIdx.x * 128;
    int ar = tid >> 1;
    int ak = (tid & 1) * 8;
    int ty = tid >> 4, tx = tid & 15;
    const float* Ag = g_hs + (size_t)(mb + ar) * 512 + ak;
    const float* Bg = fcw + (size_t)(nb + ar) * 512 + ak;

    unsigned long long acc[8][4];
#pragma unroll
    for (int i = 0; i < 8; i++)
#pragma unroll
        for (int jj = 0; jj < 4; jj++) acc[i][jj] = 0ull;

    for (int kt = 0; kt < 512; kt += 16) {
        float4 a0 = *(const float4*)(Ag + kt);
        float4 a1 = *(const float4*)(Ag + kt + 4);
        float4 b0 = *(const float4*)(Bg + kt);
        float4 b1 = *(const float4*)(Bg + kt + 4);
        __syncthreads();
        As[ak + 0][ar] = a0.x; As[ak + 1][ar] = a0.y; As[ak + 2][ar] = a0.z; As[ak + 3][ar] = a0.w;
        As[ak + 4][ar] = a1.x; As[ak + 5][ar] = a1.y; As[ak + 6][ar] = a1.z; As[ak + 7][ar] = a1.w;
        Bs[ak + 0][ar] = b0.x; Bs[ak + 1][ar] = b0.y; Bs[ak + 2][ar] = b0.z; Bs[ak + 3][ar] = b0.w;
        Bs[ak + 4][ar] = b1.x; Bs[ak + 5][ar] = b1.y; Bs[ak + 6][ar] = b1.z; Bs[ak + 7][ar] = b1.w;
        __syncthreads();
#pragma unroll
        for (int k = 0; k < 16; k++) {
            float4 av0 = *(const float4*)&As[k][ty * 8];
            float4 av1 = *(const float4*)&As[k][ty * 8 + 4];
            ulonglong2 bb0 = *(const ulonglong2*)&Bs[k][tx * 8];
            ulonglong2 bb1 = *(const ulonglong2*)&Bs[k][tx * 8 + 4];
            unsigned long long bv0 = bb0.x, bv1 = bb0.y, bv2 = bb1.x, bv3 = bb1.y;
            float a[8] = {av0.x, av0.y, av0.z, av0.w, av1.x, av1.y, av1.z, av1.w};
#pragma unroll
            for (int i = 0; i < 8; i++) {
                unsigned long long aa = pack2(a[i], a[i]);
                FMA2(acc[i][0], aa, bv0);
                FMA2(acc[i][1], aa, bv1);
                FMA2(acc[i][2], aa, bv2);
                FMA2(acc[i][3], aa, bv3);
            }
        }
    }

    int m0 = mb + ty * 8;
    int n0 = nb + tx * 8;
    float4 e0 = *(const float4*)(fcb + n0);
    float4 e1 = *(const float4*)(fcb + n0 + 4);
    float bias[8] = {e0.x, e0.y, e0.z, e0.w, e1.x, e1.y, e1.z, e1.w};
#pragma unroll
    for (int i = 0; i < 8; i++) {
        float c[8];
        unpack2(acc[i][0], c[0], c[1]);
        unpack2(acc[i][1], c[2], c[3]);
        unpack2(acc[i][2], c[4], c[5]);
        unpack2(acc[i][3], c[6], c[7]);
        float4 o0 = make_float4(c[0] + bias[0], c[1] + bias[1], c[2] + bias[2], c[3] + bias[3]);
        float4 o1 = make_float4(c[4] + bias[4], c[5] + bias[5], c[6] + bias[6], c[7] + bias[7]);
        size_t ro = (size_t)(m0 + i) * 32000 + n0;
        *(float4*)(out + ro) = o0;
        *(float4*)(out + ro + 4) = o1;
    }
}

// ---------------- launch ----------------
extern "C" void kernel_launch(void* const* d_in, const int* in_sizes, int n_in,
                              void* d_out, int out_size) {
    (void)in_sizes; (void)n_in; (void)out_size;
    const float* features = (const float*)d_in[0];
    const int*   captions = (const int*)d_in[1];
    const float* enc   = (const float*)d_in[3];
    const float* table = (const float*)d_in[4];
    const float* ft1w  = (const float*)d_in[5];
    const float* ft1b  = (const float*)d_in[6];
    const float* ft2w  = (const float*)d_in[7];
    const float* ft2b  = (const float*)d_in[8];
    const float* wih0  = (const float*)d_in[9];
    const float* whh0  = (const float*)d_in[10];
    const float* bih0  = (const float*)d_in[11];
    const float* bhh0  = (const float*)d_in[12];
    const float* wih1  = (const float*)d_in[13];
    const float* whh1  = (const float*)d_in[14];
    const float* bih1  = (const float*)d_in[15];
    const float* bhh1  = (const float*)d_in[16];
    const float* fcw   = (const float*)d_in[17];
    const float* fcb   = (const float*)d_in[18];
    float* out = (float*)d_out;

    prepW0_kernel<<<dim3(64, 48), 256>>>(wih0, whh0);
    prepW1_kernel<<<dim3(64, 32), 256>>>(wih1, whh1);
    prepB_kernel<<<8, 256>>>(bih0, bhh0, bih1, bhh1);
    embed_kernel<<<4096, 256>>>(captions, table);
    feat1_kernel<<<2048, 256>>>(features, ft1w, ft1b);
    feat2_kernel<<<2048, 256>>>(ft2w, ft2b);

    rnn_kernel<<<NCTA, 256>>>(enc);

    fc_kernel<<<dim3(250, 16), 256>>>(fcw, fcb, out);
}

// round 6
// speedup vs baseline: 1.6431x; 1.6431x over previous
#include <cuda_runtime.h>
#include <cuda_bf16.h>
#include <math.h>
#include <stdint.h>

#define FULLMASK 0xffffffffu

// ---------------- persistent device scratch ----------------
__device__ float g_W0T[1536 * 2048];      // layer0 weights [k][j*4+gate] (k: emb|ctx|h0)
__device__ float g_W1T[1024 * 2048];      // layer1 weights [k][j*4+gate] (k: h0|h1)
__device__ float g_b0[2048];
__device__ float g_b1[2048];
__device__ float g_embT[64 * 512 * 32];   // embeddings [t][k][b]
__device__ float g_emb0[64 * 2048 * 32];  // precomputed emb @ W0e, [t][jj][b]
__device__ float g_f1[32 * 512];
__device__ float g_h0T[512 * 32];         // states [j][b]
__device__ float g_h1T[512 * 32];
__device__ float g_c0T[512 * 32];
__device__ float g_c1T[512 * 32];
__device__ float g_ctxT[512 * 32];
__device__ float g_part0[16 * 2048 * 32]; // [ks][jj][b]
__device__ float g_part1[16 * 2048 * 32];
__device__ float g_hs[2048 * 512];        // FC input fp32, row m = t*32+b
// bf16 split operands for tensor-core FC
__device__ __align__(16) __nv_bfloat16 g_hsH[2048 * 512];
__device__ __align__(16) __nv_bfloat16 g_hsL[2048 * 512];
__device__ __align__(16) __nv_bfloat16 g_fcwH[32000 * 512];
__device__ __align__(16) __nv_bfloat16 g_fcwL[32000 * 512];

// ---------------- scalar helpers ----------------
static __device__ __forceinline__ float sigmoidf_(float x) { return 1.f / (1.f + expf(-x)); }

static __device__ __forceinline__ float warp_sum(float v) {
#pragma unroll
    for (int o = 16; o; o >>= 1) v += __shfl_xor_sync(FULLMASK, v, o);
    return v;
}

static __device__ __forceinline__ unsigned long long pack2(float lo, float hi) {
    unsigned long long r;
    asm("mov.b64 %0, {%1, %2};" : "=l"(r) : "f"(lo), "f"(hi));
    return r;
}
static __device__ __forceinline__ void unpack2(unsigned long long v, float& lo, float& hi) {
    asm("mov.b64 {%0, %1}, %2;" : "=f"(lo), "=f"(hi) : "l"(v));
}
#define FMA2(acc, a, b) asm("fma.rn.f32x2 %0, %1, %2, %0;" : "+l"(acc) : "l"(a), "l"(b))

static __device__ __forceinline__ uint32_t smem_to_u32(const void* p) {
    uint32_t a;
    asm("{ .reg .u64 tmp; cvta.to.shared.u64 tmp, %1; cvt.u32.u64 %0, tmp; }" : "=r"(a) : "l"(p));
    return a;
}

#define LDMATRIX_X4(r0, r1, r2, r3, addr) \
    asm volatile("ldmatrix.sync.aligned.m8n8.x4.shared.b16 {%0,%1,%2,%3}, [%4];" \
                 : "=r"(r0), "=r"(r1), "=r"(r2), "=r"(r3) : "r"(addr))
#define LDMATRIX_X2(r0, r1, addr) \
    asm volatile("ldmatrix.sync.aligned.m8n8.x2.shared.b16 {%0,%1}, [%2];" \
                 : "=r"(r0), "=r"(r1) : "r"(addr))

#define MMA_BF16(c, a, b) \
    asm volatile("mma.sync.aligned.m16n8k16.row.col.f32.bf16.bf16.f32 " \
                 "{%0,%1,%2,%3}, {%4,%5,%6,%7}, {%8,%9}, {%0,%1,%2,%3};" \
                 : "+f"((c)[0]), "+f"((c)[1]), "+f"((c)[2]), "+f"((c)[3]) \
                 : "r"((a)[0]), "r"((a)[1]), "r"((a)[2]), "r"((a)[3]), \
                   "r"((b)[0]), "r"((b)[1]))

// ---------------- weight preprocessing (tiled transpose) ----------------
__global__ __launch_bounds__(256) void prepW0_kernel(const float* __restrict__ wih0,
                                                     const float* __restrict__ whh0) {
    __shared__ float tile[32][33];
    int jj0 = blockIdx.x * 32;
    int k0 = blockIdx.y * 32;
    int tx = threadIdx.x & 31, ty = threadIdx.x >> 5;
    for (int jjl = ty; jjl < 32; jjl += 8) {
        int jj = jj0 + jjl;
        int j = jj >> 2, g = jj & 3;
        int row = g * 512 + j;
        int k = k0 + tx;
        float v = (k < 1024) ? wih0[row * 1024 + k] : whh0[row * 512 + (k - 1024)];
        tile[jjl][tx] = v;
    }
    __syncthreads();
    for (int kl = ty; kl < 32; kl += 8)
        g_W0T[(size_t)(k0 + kl) * 2048 + jj0 + tx] = tile[tx][kl];
}

__global__ __launch_bounds__(256) void prepW1_kernel(const float* __restrict__ wih1,
                                                     const float* __restrict__ whh1) {
    __shared__ float tile[32][33];
    int jj0 = blockIdx.x * 32;
    int k0 = blockIdx.y * 32;
    int tx = threadIdx.x & 31, ty = threadIdx.x >> 5;
    for (int jjl = ty; jjl < 32; jjl += 8) {
        int jj = jj0 + jjl;
        int j = jj >> 2, g = jj & 3;
        int row = g * 512 + j;
        int k = k0 + tx;
        float v = (k < 512) ? wih1[row * 512 + k] : whh1[row * 512 + (k - 512)];
        tile[jjl][tx] = v;
    }
    __syncthreads();
    for (int kl = ty; kl < 32; kl += 8)
        g_W1T[(size_t)(k0 + kl) * 2048 + jj0 + tx] = tile[tx][kl];
}

__global__ __launch_bounds__(256) void prepB_kernel(const float* __restrict__ bih0,
                                                    const float* __restrict__ bhh0,
                                                    const float* __restrict__ bih1,
                                                    const float* __restrict__ bhh1) {
    int jj = blockIdx.x * 256 + threadIdx.x;
    int j = jj >> 2, g = jj & 3;
    int row = g * 512 + j;
    g_b0[jj] = bih0[row] + bhh0[row];
    g_b1[jj] = bih1[row] + bhh1[row];
}

// split fc weights into bf16 hi/lo
__global__ __launch_bounds__(256) void splitW_kernel(const float* __restrict__ fcw) {
    int idx = blockIdx.x * 256 + threadIdx.x;   // < 32000*512
    float v = fcw[idx];
    __nv_bfloat16 h = __float2bfloat16(v);
    g_fcwH[idx] = h;
    g_fcwL[idx] = __float2bfloat16(v - __bfloat162float(h));
}

__global__ __launch_bounds__(256) void splitHS_kernel() {
    int idx = blockIdx.x * 256 + threadIdx.x;   // < 2048*512
    float v = g_hs[idx];
    __nv_bfloat16 h = __float2bfloat16(v);
    g_hsH[idx] = h;
    g_hsL[idx] = __float2bfloat16(v - __bfloat162float(h));
}

// ---------------- embedding gather: embT[t][k][b] ----------------
__global__ __launch_bounds__(256) void embed_kernel(const int* __restrict__ cap,
                                                    const float* __restrict__ table) {
    int idx = blockIdx.x * 256 + threadIdx.x;
    int b = idx >> 15;
    int t = (idx >> 9) & 63;
    int k = idx & 511;
    int tok = cap[b * 64 + t];
    g_embT[(t * 512 + k) * 32 + b] = table[(size_t)tok * 512 + k];
}

// ---------------- feature MLP ----------------
__global__ __launch_bounds__(256) void feat1_kernel(const float* __restrict__ features,
                                                    const float* __restrict__ w,
                                                    const float* __restrict__ bias) {
    int gid = blockIdx.x * 8 + (threadIdx.x >> 5);
    int lane = threadIdx.x & 31;
    int b = gid >> 9, j = gid & 511;
    const float* fr = features + b * 2048;
    const float* wr = w + j * 2048;
    float a = 0.f;
    for (int k = lane; k < 2048; k += 32) a = fmaf(fr[k], wr[k], a);
    a = warp_sum(a);
    if (!lane) g_f1[gid] = fmaxf(a + bias[j], 0.f);
}

__global__ __launch_bounds__(256) void feat2_kernel(const float* __restrict__ w,
                                                    const float* __restrict__ bias) {
    int gid = blockIdx.x * 8 + (threadIdx.x >> 5);
    int lane = threadIdx.x & 31;
    int b = gid >> 9, j = gid & 511;
    const float* fr = g_f1 + b * 512;
    const float* wr = w + j * 512;
    float a = 0.f;
    for (int k = lane; k < 512; k += 32) a = fmaf(fr[k], wr[k], a);
    a = warp_sum(a);
    if (!lane) {
        float v = a + bias[j];
        int jb = j * 32 + b;
        g_h0T[jb] = v;
        g_h1T[jb] = v;
        g_c0T[jb] = v;
        g_c1T[jb] = v;
    }
}

// ---------------- precompute emb @ W0e for all t ----------------
__global__ __launch_bounds__(256) void lstm0_pre_kernel() {
    __shared__ float xs[64 * 32];
    int jx = blockIdx.x, t = blockIdx.y;
    int tid = threadIdx.x;
    int j = tid & 63, bg = tid >> 6;
    int jjbase = (jx * 64 + j) * 4;
    const float* embt = g_embT + (size_t)t * 512 * 32;

    unsigned long long acc[4][4];
#pragma unroll
    for (int g = 0; g < 4; g++)
#pragma unroll
        for (int p = 0; p < 4; p++) acc[g][p] = 0ull;

    for (int ck = 0; ck < 8; ck++) {
        __syncthreads();
        for (int i = tid; i < 64 * 32; i += 256) xs[i] = embt[ck * 2048 + i];
        __syncthreads();
        const float4* W = (const float4*)(g_W0T + (size_t)(ck * 64) * 2048 + jjbase);
        const float* xr = xs + bg * 8;
#pragma unroll 4
        for (int k = 0; k < 64; k++) {
            float4 w = W[(size_t)k * 512];
            unsigned long long wx = pack2(w.x, w.x);
            unsigned long long wy = pack2(w.y, w.y);
            unsigned long long wz = pack2(w.z, w.z);
            unsigned long long ww = pack2(w.w, w.w);
            const unsigned long long* xp = (const unsigned long long*)(xr + k * 32);
#pragma unroll
            for (int p = 0; p < 4; p++) {
                unsigned long long xv = xp[p];
                FMA2(acc[0][p], wx, xv);
                FMA2(acc[1][p], wy, xv);
                FMA2(acc[2][p], wz, xv);
                FMA2(acc[3][p], ww, xv);
            }
        }
    }
#pragma unroll
    for (int g = 0; g < 4; g++) {
        float* dst = g_emb0 + ((size_t)t * 2048 + jjbase + g) * 32 + bg * 8;
#pragma unroll
        for (int p = 0; p < 4; p++) {
            float lo, hi;
            unpack2(acc[g][p], lo, hi);
            *(float2*)(dst + 2 * p) = make_float2(lo, hi);
        }
    }
}

// ---------------- attention (one block per batch element) ----------------
__global__ __launch_bounds__(256) void attn_kernel(const float* __restrict__ enc) {
    __shared__ float q[512];
    __shared__ float sc[196];
    __shared__ float redv[16];
    int b = blockIdx.x;
    int tid = threadIdx.x, lane = tid & 31, wid = tid >> 5;

    for (int i = tid; i < 512; i += 256) q[i] = g_h1T[i * 32 + b];
    __syncthreads();

    for (int s = wid; s < 196; s += 8) {
        const float* e = enc + ((size_t)b * 196 + s) * 512;
        float a = 0.f;
        for (int k = lane; k < 512; k += 32) a = fmaf(q[k], e[k], a);
        a = warp_sum(a);
        if (!lane) sc[s] = a * 0.04419417382415922f;
    }
    __syncthreads();

    float v = (tid < 196) ? sc[tid] : -1e30f;
    float m = v;
#pragma unroll
    for (int o = 16; o; o >>= 1) m = fmaxf(m, __shfl_xor_sync(FULLMASK, m, o));
    if (!lane) redv[wid] = m;
    __syncthreads();
    m = redv[0];
#pragma unroll
    for (int i = 1; i < 8; i++) m = fmaxf(m, redv[i]);
    float ev = (tid < 196) ? expf(v - m) : 0.f;
    float s = warp_sum(ev);
    if (!lane) redv[8 + wid] = s;
    __syncthreads();
    s = 0.f;
#pragma unroll
    for (int i = 0; i < 8; i++) s += redv[8 + i];
    if (tid < 196) sc[tid] = ev / s;
    __syncthreads();

    for (int j = tid; j < 512; j += 256) {
        const float* e = enc + (size_t)b * 196 * 512 + j;
        float a = 0.f;
#pragma unroll 4
        for (int ss = 0; ss < 196; ss++) a = fmaf(sc[ss], e[(size_t)ss * 512], a);
        g_ctxT[j * 32 + b] = a;
    }
}

// ---------------- LSTM matmul kernels (batched over b, k-split) ----------------
__global__ __launch_bounds__(256) void lstm0_mm_kernel() {
    __shared__ float xs[64 * 32];
    int jx = blockIdx.x, ks = blockIdx.y;
    int tid = threadIdx.x;
    int j = tid & 63, bg = tid >> 6;

    for (int i = tid; i < 64 * 32; i += 256) {
        int kl = i >> 5, b = i & 31;
        int kk = ks * 64 + kl;     // 0..1023 over [ctx | h0]
        float v = (kk < 512) ? g_ctxT[kk * 32 + b] : g_h0T[(kk - 512) * 32 + b];
        xs[i] = v;
    }
    __syncthreads();

    int jjbase = (jx * 64 + j) * 4;
    const float4* W = (const float4*)(g_W0T + (size_t)(512 + ks * 64) * 2048 + jjbase);

    unsigned long long acc[4][4];
#pragma unroll
    for (int g = 0; g < 4; g++)
#pragma unroll
        for (int p = 0; p < 4; p++) acc[g][p] = 0ull;

    const float* xr = xs + bg * 8;
#pragma unroll 4
    for (int k = 0; k < 64; k++) {
        float4 w = W[(size_t)k * 512];
        unsigned long long wx = pack2(w.x, w.x);
        unsigned long long wy = pack2(w.y, w.y);
        unsigned long long wz = pack2(w.z, w.z);
        unsigned long long ww = pack2(w.w, w.w);
        const unsigned long long* xp = (const unsigned long long*)(xr + k * 32);
#pragma unroll
        for (int p = 0; p < 4; p++) {
            unsigned long long xv = xp[p];
            FMA2(acc[0][p], wx, xv);
            FMA2(acc[1][p], wy, xv);
            FMA2(acc[2][p], wz, xv);
            FMA2(acc[3][p], ww, xv);
        }
    }

#pragma unroll
    for (int g = 0; g < 4; g++) {
        float* dst = g_part0 + ((size_t)ks * 2048 + jjbase + g) * 32 + bg * 8;
#pragma unroll
        for (int p = 0; p < 4; p++) {
            float lo, hi;
            unpack2(acc[g][p], lo, hi);
            *(float2*)(dst + 2 * p) = make_float2(lo, hi);
        }
    }
}

__global__ __launch_bounds__(256) void lstm1_mm_kernel() {
    __shared__ float xs[64 * 32];
    int jx = blockIdx.x, ks = blockIdx.y;
    int tid = threadIdx.x;
    int j = tid & 63, bg = tid >> 6;

    for (int i = tid; i < 64 * 32; i += 256) {
        int kl = i >> 5, b = i & 31;
        int kk = ks * 64 + kl;     // 0..1023 over [h0 | h1]
        float v = (kk < 512) ? g_h0T[kk * 32 + b] : g_h1T[(kk - 512) * 32 + b];
        xs[i] = v;
    }
    __syncthreads();

    int jjbase = (jx * 64 + j) * 4;
    const float4* W = (const float4*)(g_W1T + (size_t)(ks * 64) * 2048 + jjbase);

    unsigned long long acc[4][4];
#pragma unroll
    for (int g = 0; g < 4; g++)
#pragma unroll
        for (int p = 0; p < 4; p++) acc[g][p] = 0ull;

    const float* xr = xs + bg * 8;
#pragma unroll 4
    for (int k = 0; k < 64; k++) {
        float4 w = W[(size_t)k * 512];
        unsigned long long wx = pack2(w.x, w.x);
        unsigned long long wy = pack2(w.y, w.y);
        unsigned long long wz = pack2(w.z, w.z);
        unsigned long long ww = pack2(w.w, w.w);
        const unsigned long long* xp = (const unsigned long long*)(xr + k * 32);
#pragma unroll
        for (int p = 0; p < 4; p++) {
            unsigned long long xv = xp[p];
            FMA2(acc[0][p], wx, xv);
            FMA2(acc[1][p], wy, xv);
            FMA2(acc[2][p], wz, xv);
            FMA2(acc[3][p], ww, xv);
        }
    }

#pragma unroll
    for (int g = 0; g < 4; g++) {
        float* dst = g_part1 + ((size_t)ks * 2048 + jjbase + g) * 32 + bg * 8;
#pragma unroll
        for (int p = 0; p < 4; p++) {
            float lo, hi;
            unpack2(acc[g][p], lo, hi);
            *(float2*)(dst + 2 * p) = make_float2(lo, hi);
        }
    }
}

// ---------------- gate epilogues ----------------
__global__ __launch_bounds__(256) void lstm0_red_kernel(int t) {
    int idx = blockIdx.x * 256 + threadIdx.x;  // < 16384
    int j = idx >> 5, b = idx & 31;
    float s[4];
    const float* e0 = g_emb0 + ((size_t)t * 2048 + j * 4) * 32 + b;
#pragma unroll
    for (int g = 0; g < 4; g++) s[g] = g_b0[j * 4 + g] + e0[g * 32];
#pragma unroll
    for (int ks = 0; ks < 16; ks++) {
        const float* p = g_part0 + ((size_t)ks * 2048 + j * 4) * 32 + b;
#pragma unroll
        for (int g = 0; g < 4; g++) s[g] += p[g * 32];
    }
    float gi = sigmoidf_(s[0]);
    float gf = sigmoidf_(s[1]);
    float gg = tanhf(s[2]);
    float go = sigmoidf_(s[3]);
    int jb = j * 32 + b;
    float c2 = gf * g_c0T[jb] + gi * gg;
    g_c0T[jb] = c2;
    g_h0T[jb] = go * tanhf(c2);
}

__global__ __launch_bounds__(256) void lstm1_red_kernel(int t) {
    int idx = blockIdx.x * 256 + threadIdx.x;  // < 16384
    int j = idx >> 5, b = idx & 31;
    float s[4];
#pragma unroll
    for (int g = 0; g < 4; g++) s[g] = g_b1[j * 4 + g];
#pragma unroll
    for (int ks = 0; ks < 16; ks++) {
        const float* p = g_part1 + ((size_t)ks * 2048 + j * 4) * 32 + b;
#pragma unroll
        for (int g = 0; g < 4; g++) s[g] += p[g * 32];
    }
    float gi = sigmoidf_(s[0]);
    float gf = sigmoidf_(s[1]);
    float gg = tanhf(s[2]);
    float go = sigmoidf_(s[3]);
    int jb = j * 32 + b;
    float c2 = gf * g_c1T[jb] + gi * gg;
    g_c1T[jb] = c2;
    float h = go * tanhf(c2);
    g_h1T[jb] = h;
    g_hs[((size_t)t * 32 + b) * 512 + j] = h;
}

// ---------------- tensor-core FC via mma.sync bf16 split ----------------
// out[2048,32000] = hs @ fcw^T + b.  3-term split: AhBh + AhBl + AlBh, fp32 acc.
// CTA tile 128x128, K chunks of 64. Smem: Ah|Al|Bh|Bl, 16KB each, SW128 swizzle.
__global__ __launch_bounds__(256, 1) void fc_mma_kernel(const float* __restrict__ fcb,
                                                        float* __restrict__ out) {
    extern __shared__ char smem[];
    uint32_t sbase = smem_to_u32(smem);
    int tid = threadIdx.x, lane = tid & 31, wid = tid >> 5;
    int mb = blockIdx.y * 128, nb = blockIdx.x * 128;
    int warp_m = (wid & 1) * 64, warp_n = (wid >> 1) * 32;

    float acc[4][4][4];
#pragma unroll
    for (int mi = 0; mi < 4; mi++)
#pragma unroll
        for (int nj = 0; nj < 4; nj++)
#pragma unroll
            for (int r = 0; r < 4; r++) acc[mi][nj][r] = 0.f;

    for (int kc = 0; kc < 8; kc++) {
        __syncthreads();
#pragma unroll
        for (int it = 0; it < 16; it++) {
            int s = tid + it * 256;                 // < 4096
            int tile = s >> 10, r = (s >> 3) & 127, c = s & 7;
            const __nv_bfloat16* g;
            if (tile == 0)      g = g_hsH + (size_t)(mb + r) * 512;
            else if (tile == 1) g = g_hsL + (size_t)(mb + r) * 512;
            else if (tile == 2) g = g_fcwH + (size_t)(nb + r) * 512;
            else                g = g_fcwL + (size_t)(nb + r) * 512;
            uint4 v = *(const uint4*)(g + kc * 64 + c * 8);
            uint32_t off = (uint32_t)(r * 128 + c * 16);
            off ^= (off >> 3) & 0x70;
            *(uint4*)(smem + tile * 16384 + off) = v;
        }
        __syncthreads();

#pragma unroll
        for (int ka = 0; ka < 4; ka++) {
            uint32_t a_hi[4][4], a_lo[4][4], b_hi[4][2], b_lo[4][2];
            int rA = warp_m + (lane & 15);
            int sA = ka * 2 + (lane >> 4);
#pragma unroll
            for (int mi = 0; mi < 4; mi++) {
                uint32_t off = (uint32_t)((rA + mi * 16) * 128 + sA * 16);
                off ^= (off >> 3) & 0x70;
                LDMATRIX_X4(a_hi[mi][0], a_hi[mi][1], a_hi[mi][2], a_hi[mi][3], sbase + off);
                LDMATRIX_X4(a_lo[mi][0], a_lo[mi][1], a_lo[mi][2], a_lo[mi][3],
                            sbase + 16384 + off);
            }
            int rB = warp_n + (lane & 7);
            int sB = ka * 2 + ((lane >> 3) & 1);
#pragma unroll
            for (int nj = 0; nj < 4; nj++) {
                uint32_t off = (uint32_t)((rB + nj * 8) * 128 + sB * 16);
                off ^= (off >> 3) & 0x70;
                LDMATRIX_X2(b_hi[nj][0], b_hi[nj][1], sbase + 32768 + off);
                LDMATRIX_X2(b_lo[nj][0], b_lo[nj][1], sbase + 49152 + off);
            }
#pragma unroll
            for (int mi = 0; mi < 4; mi++)
#pragma unroll
                for (int nj = 0; nj < 4; nj++) {
                    MMA_BF16(acc[mi][nj], a_hi[mi], b_hi[nj]);
                    MMA_BF16(acc[mi][nj], a_hi[mi], b_lo[nj]);
                    MMA_BF16(acc[mi][nj], a_lo[mi], b_hi[nj]);
                }
        }
    }

    // epilogue: C atom (mi,nj): c0=(row g, col q*2), c1=(g, q*2+1), c2=(g+8, q*2), c3=(g+8, q*2+1)
    int g = lane >> 2, q = lane & 3;
#pragma unroll
    for (int mi = 0; mi < 4; mi++) {
#pragma unroll
        for (int nj = 0; nj < 4; nj++) {
            int m = mb + warp_m + mi * 16 + g;
            int n = nb + warp_n + nj * 8 + q * 2;
            float2 bb = *(const float2*)(fcb + n);
            *(float2*)(out + (size_t)m * 32000 + n) =
                make_float2(acc[mi][nj][0] + bb.x, acc[mi][nj][1] + bb.y);
            *(float2*)(out + (size_t)(m + 8) * 32000 + n) =
                make_float2(acc[mi][nj][2] + bb.x, acc[mi][nj][3] + bb.y);
        }
    }
}

// ---------------- launch ----------------
extern "C" void kernel_launch(void* const* d_in, const int* in_sizes, int n_in,
                              void* d_out, int out_size) {
    (void)in_sizes; (void)n_in; (void)out_size;
    const float* features = (const float*)d_in[0];
    const int*   captions = (const int*)d_in[1];
    const float* enc   = (const float*)d_in[3];
    const float* table = (const float*)d_in[4];
    const float* ft1w  = (const float*)d_in[5];
    const float* ft1b  = (const float*)d_in[6];
    const float* ft2w  = (const float*)d_in[7];
    const float* ft2b  = (const float*)d_in[8];
    const float* wih0  = (const float*)d_in[9];
    const float* whh0  = (const float*)d_in[10];
    const float* bih0  = (const float*)d_in[11];
    const float* bhh0  = (const float*)d_in[12];
    const float* wih1  = (const float*)d_in[13];
    const float* whh1  = (const float*)d_in[14];
    const float* bih1  = (const float*)d_in[15];
    const float* bhh1  = (const float*)d_in[16];
    const float* fcw   = (const float*)d_in[17];
    const float* fcb   = (const float*)d_in[18];
    float* out = (float*)d_out;

    static int smem_set = 0;
    if (!smem_set) {
        cudaFuncSetAttribute(fc_mma_kernel, cudaFuncAttributeMaxDynamicSharedMemorySize, 65536);
        smem_set = 1;
    }

    prepW0_kernel<<<dim3(64, 48), 256>>>(wih0, whh0);
    prepW1_kernel<<<dim3(64, 32), 256>>>(wih1, whh1);
    prepB_kernel<<<8, 256>>>(bih0, bhh0, bih1, bhh1);
    embed_kernel<<<4096, 256>>>(captions, table);
    feat1_kernel<<<2048, 256>>>(features, ft1w, ft1b);
    feat2_kernel<<<2048, 256>>>(ft2w, ft2b);
    splitW_kernel<<<64000, 256>>>(fcw);
    lstm0_pre_kernel<<<dim3(8, 64), 256>>>();

    for (int t = 0; t < 64; t++) {
        attn_kernel<<<32, 256>>>(enc);
        lstm0_mm_kernel<<<dim3(8, 16), 256>>>();
        lstm0_red_kernel<<<64, 256>>>(t);
        lstm1_mm_kernel<<<dim3(8, 16), 256>>>();
        lstm1_red_kernel<<<64, 256>>>(t);
    }

    splitHS_kernel<<<4096, 256>>>();
    fc_mma_kernel<<<dim3(250, 16), 256, 65536>>>(fcb, out);
}